// round 1
// baseline (speedup 1.0000x reference)
#include <cuda_runtime.h>
#include <math.h>

#define NROWS 16384   // B*T = 32*512
#define E     512
#define H     8
#define BN_EPS 1e-5f
#define GAMMA  1.5f
#define NCHUNK 64     // BN partial chunks

// Scratch (static device arrays — no allocation)
__device__ float g_logits[(size_t)H * NROWS * E];  // 268 MB
__device__ float g_psum[H * NCHUNK * E];
__device__ float g_psq [H * NCHUNK * E];
__device__ float g_scale[H * E];
__device__ float g_shift[H * E];

// ---------------------------------------------------------------------------
// GEMM: logits[h][n][o] = sum_k x[n][k] * W[h][o][k]   (NT, fp32 SIMT tiled)
// 64x64 tile, BK=16, 256 threads, 4x4 per thread.
// ---------------------------------------------------------------------------
__global__ void __launch_bounds__(256) gemm_kernel(const float* __restrict__ A,
                                                   const float* __restrict__ Wt) {
    __shared__ float As[16][64];
    __shared__ float Bs[16][64];

    const int h  = blockIdx.z;
    const int m0 = blockIdx.x * 64;
    const int o0 = blockIdx.y * 64;
    const float* Bh = Wt + (size_t)h * E * E;

    const int tid = threadIdx.x;
    const int tm  = (tid >> 4) * 4;   // 0..60
    const int tn  = (tid & 15) * 4;   // 0..60
    const int lr  = tid >> 2;         // 0..63 (load row)
    const int lc  = (tid & 3) * 4;    // 0,4,8,12 (load col base)

    float acc[4][4] = {};

    for (int k0 = 0; k0 < E; k0 += 16) {
        float4 a = *(const float4*)(A  + (size_t)(m0 + lr) * E + k0 + lc);
        float4 b = *(const float4*)(Bh + (size_t)(o0 + lr) * E + k0 + lc);
        As[lc+0][lr] = a.x; As[lc+1][lr] = a.y; As[lc+2][lr] = a.z; As[lc+3][lr] = a.w;
        Bs[lc+0][lr] = b.x; Bs[lc+1][lr] = b.y; Bs[lc+2][lr] = b.z; Bs[lc+3][lr] = b.w;
        __syncthreads();

        #pragma unroll
        for (int k = 0; k < 16; k++) {
            float4 ar = *(const float4*)&As[k][tm];
            float4 br = *(const float4*)&Bs[k][tn];
            float av[4] = {ar.x, ar.y, ar.z, ar.w};
            float bv[4] = {br.x, br.y, br.z, br.w};
            #pragma unroll
            for (int i = 0; i < 4; i++)
                #pragma unroll
                for (int j = 0; j < 4; j++)
                    acc[i][j] = fmaf(av[i], bv[j], acc[i][j]);
        }
        __syncthreads();
    }

    float* C = g_logits + (size_t)h * NROWS * E;
    #pragma unroll
    for (int i = 0; i < 4; i++) {
        float4 st = make_float4(acc[i][0], acc[i][1], acc[i][2], acc[i][3]);
        *(float4*)(C + (size_t)(m0 + tm + i) * E + o0 + tn) = st;
    }
}

// ---------------------------------------------------------------------------
// BN batch stats, stage 1: deterministic partial sums over n-chunks of 256.
// grid = H*NCHUNK blocks, 512 threads (one per o).
// ---------------------------------------------------------------------------
__global__ void __launch_bounds__(512) bnstats_kernel() {
    const int h     = blockIdx.x >> 6;
    const int chunk = blockIdx.x & 63;
    const int o     = threadIdx.x;
    const float* L  = g_logits + ((size_t)h * NROWS + (size_t)chunk * 256) * E + o;
    float s = 0.f, s2 = 0.f;
    for (int r = 0; r < 256; r++) {
        float v = L[(size_t)r * E];
        s  += v;
        s2 = fmaf(v, v, s2);
    }
    g_psum[(h * NCHUNK + chunk) * E + o] = s;
    g_psq [(h * NCHUNK + chunk) * E + o] = s2;
}

// ---------------------------------------------------------------------------
// BN stage 2: fold mean/var + affine into per-(h,o) scale/shift.
// ---------------------------------------------------------------------------
__global__ void __launch_bounds__(512) finalize_kernel(const float* __restrict__ bw,
                                                       const float* __restrict__ bb) {
    const int h = blockIdx.x;
    const int o = threadIdx.x;
    float s = 0.f, s2 = 0.f;
    for (int c = 0; c < NCHUNK; c++) {
        s  += g_psum[(h * NCHUNK + c) * E + o];
        s2 += g_psq [(h * NCHUNK + c) * E + o];
    }
    const float inv_n = 1.0f / (float)NROWS;
    float mean = s * inv_n;
    float var  = fmaf(-mean, mean, s2 * inv_n);
    float istd = rsqrtf(var + BN_EPS);
    float sc   = bw[h * E + o] * istd;
    g_scale[h * E + o] = sc;
    g_shift[h * E + o] = fmaf(-mean, sc, bb[h * E + o]);
}

// ---------------------------------------------------------------------------
// Sequential head scan with sparsemax. One warp per row (n); 16 elems/lane.
// Sparsemax tau via Newton on f(tau)=sum relu(z-tau)-1 (exact for piecewise
// linear f once the support stabilizes; start tau = max(z)-1 has f>=0).
// ---------------------------------------------------------------------------
__global__ void __launch_bounds__(256) scan_kernel(const float* __restrict__ x,
                                                   float* __restrict__ out_masked,
                                                   float* __restrict__ out_masks) {
    const int gw   = (blockIdx.x * blockDim.x + threadIdx.x) >> 5;
    const int lane = threadIdx.x & 31;
    if (gw >= NROWS) return;
    const int n = gw;
    const int b = n >> 9;     // T = 512
    const int t = n & 511;

    float xr[16], prior[16];
    const float* xp = x + (size_t)n * E;
    #pragma unroll
    for (int j = 0; j < 16; j++) {
        xr[j]    = xp[lane + 32 * j];
        prior[j] = 1.0f;
    }

    for (int h = 0; h < H; h++) {
        const float* Lp  = g_logits + ((size_t)h * NROWS + n) * E;
        const float* scp = g_scale + h * E;
        const float* shp = g_shift + h * E;

        float z[16];
        float m = -1e30f;
        #pragma unroll
        for (int j = 0; j < 16; j++) {
            const int o = lane + 32 * j;
            float v = fmaf(Lp[o], scp[o], shp[o]) * prior[j];
            z[j] = v;
            m = fmaxf(m, v);
        }
        #pragma unroll
        for (int off = 16; off; off >>= 1)
            m = fmaxf(m, __shfl_xor_sync(0xffffffffu, m, off));

        float tau = m - 1.0f;
        for (int it = 0; it < 64; it++) {
            float S = 0.f, K = 0.f;
            #pragma unroll
            for (int j = 0; j < 16; j++) {
                if (z[j] > tau) { S += z[j]; K += 1.0f; }
            }
            #pragma unroll
            for (int off = 16; off; off >>= 1) {
                S += __shfl_xor_sync(0xffffffffu, S, off);
                K += __shfl_xor_sync(0xffffffffu, K, off);
            }
            float tnew = (S - 1.0f) / K;   // K >= 1 always (max elem in support)
            if (!(tnew > tau)) break;      // converged (exact root reached)
            tau = tnew;
        }

        float* om = out_masked + ((size_t)h * NROWS + n) * E;                 // (H,B,T,E)
        float* ok = out_masks  + (((size_t)b * H + h) * 512 + t) * E;         // (B,H,T,E)
        #pragma unroll
        for (int j = 0; j < 16; j++) {
            const int o = lane + 32 * j;
            float mask = fmaxf(z[j] - tau, 0.0f);
            om[o] = xr[j] * mask;
            ok[o] = mask;
            prior[j] *= fmaxf(GAMMA - mask, 0.0f);
        }
    }
}

// ---------------------------------------------------------------------------
extern "C" void kernel_launch(void* const* d_in, const int* in_sizes, int n_in,
                              void* d_out, int out_size) {
    const float* x  = (const float*)d_in[0];   // (32,512,512)
    const float* W  = (const float*)d_in[1];   // (8,512,512)
    const float* bw = (const float*)d_in[2];   // (8,512)
    const float* bb = (const float*)d_in[3];   // (8,512)
    float* out = (float*)d_out;
    float* out_masked = out;                               // (H,B,T,E)
    float* out_masks  = out + (size_t)H * NROWS * E;       // (B,H,T,E)

    dim3 ggrid(NROWS / 64, E / 64, H);
    gemm_kernel<<<ggrid, 256>>>(x, W);
    bnstats_kernel<<<H * NCHUNK, 512>>>();
    finalize_kernel<<<H, 512>>>(bw, bb);
    scan_kernel<<<NROWS / 8, 256>>>(x, out_masked, out_masks);
}

// round 3
// speedup vs baseline: 3.1980x; 3.1980x over previous
#include <cuda_runtime.h>
#include <cuda_bf16.h>
#include <math.h>
#include <stdint.h>

#define NROWS 16384   // B*T
#define E     512
#define H     8
#define BN_EPS 1e-5f
#define GAMMA  1.5f
#define NCHUNK 64

#define BM 128
#define BN 128
#define BK 64
#define TILE_BYTES (BM * BK * 2)      // 16384
#define STAGE_BYTES (4 * TILE_BYTES)  // 65536 (Ahi,Alo,Bhi,Blo)
#define SMEM_TOTAL (2 * STAGE_BYTES)  // 131072

// ---------------- static device scratch (no allocation) ----------------
__device__ float g_logits[(size_t)H * NROWS * E];   // 268 MB
__device__ float g_psum[H * NCHUNK * E];
__device__ float g_psq [H * NCHUNK * E];
__device__ float g_scale[H * E];
__device__ float g_shift[H * E];
__device__ __nv_bfloat16 g_xhi[(size_t)NROWS * E];
__device__ __nv_bfloat16 g_xlo[(size_t)NROWS * E];
__device__ __nv_bfloat16 g_whi[(size_t)H * E * E];
__device__ __nv_bfloat16 g_wlo[(size_t)H * E * E];

// ---------------- PTX helpers ----------------
static __device__ __forceinline__ uint32_t smem_u32(const void* p) {
    uint32_t a;
    asm("{ .reg .u64 t; cvta.to.shared.u64 t, %1; cvt.u32.u64 %0, t; }" : "=r"(a) : "l"(p));
    return a;
}
static __device__ __forceinline__ void cp_async16(uint32_t dst, const void* src) {
    asm volatile("cp.async.cg.shared.global [%0], [%1], 16;" :: "r"(dst), "l"(src) : "memory");
}
static __device__ __forceinline__ void cp_commit() {
    asm volatile("cp.async.commit_group;" ::: "memory");
}
template <int N>
static __device__ __forceinline__ void cp_wait() {
    asm volatile("cp.async.wait_group %0;" :: "n"(N) : "memory");
}
static __device__ __forceinline__ void ldsm4(uint32_t* r, uint32_t addr) {
    asm volatile("ldmatrix.sync.aligned.m8n8.x4.shared.b16 {%0,%1,%2,%3}, [%4];"
                 : "=r"(r[0]), "=r"(r[1]), "=r"(r[2]), "=r"(r[3]) : "r"(addr));
}
static __device__ __forceinline__ void mma16816(float* d, const uint32_t* a, const uint32_t* b) {
    asm volatile(
        "mma.sync.aligned.m16n8k16.row.col.f32.bf16.bf16.f32 "
        "{%0,%1,%2,%3}, {%4,%5,%6,%7}, {%8,%9}, {%0,%1,%2,%3};"
        : "+f"(d[0]), "+f"(d[1]), "+f"(d[2]), "+f"(d[3])
        : "r"(a[0]), "r"(a[1]), "r"(a[2]), "r"(a[3]), "r"(b[0]), "r"(b[1]));
}

// ---------------------------------------------------------------------------
// bf16 split kernels: v = hi + lo (each bf16-rounded)
// ---------------------------------------------------------------------------
static __device__ __forceinline__ void split4(const float4 v, __nv_bfloat16* hi, __nv_bfloat16* lo, size_t i) {
    float a[4] = {v.x, v.y, v.z, v.w};
    uint32_t ph[2], pl[2];
    #pragma unroll
    for (int p = 0; p < 2; p++) {
        __nv_bfloat16 h0 = __float2bfloat16(a[2*p+0]);
        __nv_bfloat16 h1 = __float2bfloat16(a[2*p+1]);
        __nv_bfloat16 l0 = __float2bfloat16(a[2*p+0] - __bfloat162float(h0));
        __nv_bfloat16 l1 = __float2bfloat16(a[2*p+1] - __bfloat162float(h1));
        ph[p] = ((uint32_t)__bfloat16_as_ushort(h1) << 16) | __bfloat16_as_ushort(h0);
        pl[p] = ((uint32_t)__bfloat16_as_ushort(l1) << 16) | __bfloat16_as_ushort(l0);
    }
    *(uint2*)(hi + i) = make_uint2(ph[0], ph[1]);
    *(uint2*)(lo + i) = make_uint2(pl[0], pl[1]);
}
__global__ void __launch_bounds__(256) split_x_kernel(const float* __restrict__ x) {
    size_t i = ((size_t)blockIdx.x * 256 + threadIdx.x) * 4;
    split4(*(const float4*)(x + i), g_xhi, g_xlo, i);
}
__global__ void __launch_bounds__(256) split_w_kernel(const float* __restrict__ w) {
    size_t i = ((size_t)blockIdx.x * 256 + threadIdx.x) * 4;
    split4(*(const float4*)(w + i), g_whi, g_wlo, i);
}

// ---------------------------------------------------------------------------
// HMMA GEMM: logits[h][n][o] = sum_k x[n][k]*W[h][o][k], bf16x3 split.
// CTA tile 128x128, BK=64, 2-stage cp.async, 8 warps (2x4), warp tile 64x32.
// SMEM layout per stage: [Ahi][Alo][Bhi][Blo], each 128x64 bf16, 128B rows
// with XOR-swizzle: 16B-chunk c stored at (c ^ (row & 7)).
// ---------------------------------------------------------------------------
__global__ void __launch_bounds__(256) gemm_kernel() {
    extern __shared__ __align__(1024) char smem[];
    const uint32_t sb = smem_u32(smem);
    const int tid  = threadIdx.x;
    const int lane = tid & 31;
    const int wid  = tid >> 5;
    const int wm   = wid & 1;      // 2 warps along M (64 rows each)
    const int wn   = wid >> 1;     // 4 warps along N (32 cols each)
    const int m0   = blockIdx.x * BM;
    const int o0   = blockIdx.y * BN;
    const int h    = blockIdx.z;

    const __nv_bfloat16* gsrc[4];
    gsrc[0] = g_xhi + (size_t)m0 * E;
    gsrc[1] = g_xlo + (size_t)m0 * E;
    gsrc[2] = g_whi + ((size_t)h * E + o0) * E;
    gsrc[3] = g_wlo + ((size_t)h * E + o0) * E;

    // per-thread load coords: 4 chunks per tile per stage
    const int lrow0 = tid >> 3;        // cid = tid + i*256 -> row = cid>>3
    const int lc    = tid & 7;         // chunk 0..7

    float C[4][4][4];
    #pragma unroll
    for (int i = 0; i < 4; i++)
        #pragma unroll
        for (int j = 0; j < 4; j++)
            #pragma unroll
            for (int k = 0; k < 4; k++) C[i][j][k] = 0.f;

    auto load_stage = [&](int s, int k0) {
        const uint32_t base = sb + s * STAGE_BYTES;
        #pragma unroll
        for (int t = 0; t < 4; t++) {
            const __nv_bfloat16* gp = gsrc[t] + k0 + lc * 8;
            const uint32_t tb = base + t * TILE_BYTES;
            #pragma unroll
            for (int i = 0; i < 4; i++) {
                const int row = lrow0 + i * 32;
                const uint32_t dst = tb + (row << 7) + (((lc ^ (row & 7)) & 7) << 4);
                cp_async16(dst, gp + (size_t)row * E);
            }
        }
    };

    auto compute_stage = [&](int s) {
        const uint32_t aHiB = sb + s * STAGE_BYTES;
        const uint32_t aLoB = aHiB + TILE_BYTES;
        const uint32_t bHiB = aHiB + 2 * TILE_BYTES;
        const uint32_t bLoB = aHiB + 3 * TILE_BYTES;
        #pragma unroll
        for (int ks = 0; ks < 4; ks++) {
            uint32_t ahi[4][4], alo[4][4], bhi[4][2], blo[4][2];
            #pragma unroll
            for (int mi = 0; mi < 4; mi++) {
                const int row = wm * 64 + mi * 16 + (lane & 15);
                const int ch  = ks * 2 + (lane >> 4);
                const uint32_t off = (row << 7) + (((ch ^ (row & 7)) & 7) << 4);
                ldsm4(ahi[mi], aHiB + off);
                ldsm4(alo[mi], aLoB + off);
            }
            #pragma unroll
            for (int p = 0; p < 2; p++) {
                const int row = wn * 32 + p * 16 + (lane & 7) + ((lane >> 4) << 3);
                const int ch  = ks * 2 + ((lane >> 3) & 1);
                const uint32_t off = (row << 7) + (((ch ^ (row & 7)) & 7) << 4);
                uint32_t r[4];
                ldsm4(r, bHiB + off);
                bhi[2*p][0] = r[0]; bhi[2*p][1] = r[1];
                bhi[2*p+1][0] = r[2]; bhi[2*p+1][1] = r[3];
                ldsm4(r, bLoB + off);
                blo[2*p][0] = r[0]; blo[2*p][1] = r[1];
                blo[2*p+1][0] = r[2]; blo[2*p+1][1] = r[3];
            }
            #pragma unroll
            for (int mi = 0; mi < 4; mi++)
                #pragma unroll
                for (int nj = 0; nj < 4; nj++) {
                    mma16816(C[mi][nj], ahi[mi], bhi[nj]);
                    mma16816(C[mi][nj], ahi[mi], blo[nj]);
                    mma16816(C[mi][nj], alo[mi], bhi[nj]);
                }
        }
    };

    load_stage(0, 0);
    cp_commit();
    #pragma unroll 1
    for (int c = 0; c < E / BK; c++) {
        if (c < E / BK - 1) {
            load_stage((c + 1) & 1, (c + 1) * BK);
            cp_commit();
            cp_wait<1>();
        } else {
            cp_wait<0>();
        }
        __syncthreads();
        compute_stage(c & 1);
        __syncthreads();
    }

    // Epilogue: direct fp32 stores (32B-sector aligned float2 per lane group)
    float* Cg = g_logits + (size_t)h * NROWS * E;
    const int rb = m0 + wm * 64;
    const int cb = o0 + wn * 32;
    #pragma unroll
    for (int mi = 0; mi < 4; mi++) {
        const int r = rb + mi * 16 + (lane >> 2);
        #pragma unroll
        for (int nj = 0; nj < 4; nj++) {
            const int col = cb + nj * 8 + 2 * (lane & 3);
            *(float2*)(Cg + (size_t)r * E + col)       = make_float2(C[mi][nj][0], C[mi][nj][1]);
            *(float2*)(Cg + (size_t)(r + 8) * E + col) = make_float2(C[mi][nj][2], C[mi][nj][3]);
        }
    }
}

// ---------------------------------------------------------------------------
// BN batch stats (deterministic two-stage) + finalize into scale/shift
// ---------------------------------------------------------------------------
__global__ void __launch_bounds__(512) bnstats_kernel() {
    const int h     = blockIdx.x >> 6;
    const int chunk = blockIdx.x & 63;
    const int o     = threadIdx.x;
    const float* L  = g_logits + ((size_t)h * NROWS + (size_t)chunk * 256) * E + o;
    float s = 0.f, s2 = 0.f;
    for (int r = 0; r < 256; r++) {
        float v = L[(size_t)r * E];
        s  += v;
        s2 = fmaf(v, v, s2);
    }
    g_psum[(h * NCHUNK + chunk) * E + o] = s;
    g_psq [(h * NCHUNK + chunk) * E + o] = s2;
}

__global__ void __launch_bounds__(512) finalize_kernel(const float* __restrict__ bw,
                                                       const float* __restrict__ bb) {
    const int h = blockIdx.x;
    const int o = threadIdx.x;
    float s = 0.f, s2 = 0.f;
    for (int c = 0; c < NCHUNK; c++) {
        s  += g_psum[(h * NCHUNK + c) * E + o];
        s2 += g_psq [(h * NCHUNK + c) * E + o];
    }
    const float inv_n = 1.0f / (float)NROWS;
    float mean = s * inv_n;
    float var  = fmaf(-mean, mean, s2 * inv_n);
    float istd = rsqrtf(var + BN_EPS);
    float sc   = bw[h * E + o] * istd;
    g_scale[h * E + o] = sc;
    g_shift[h * E + o] = fmaf(-mean, sc, bb[h * E + o]);
}

// ---------------------------------------------------------------------------
// Sequential head scan with sparsemax (Newton tau), one warp per row.
// ---------------------------------------------------------------------------
__global__ void __launch_bounds__(256) scan_kernel(const float* __restrict__ x,
                                                   float* __restrict__ out_masked,
                                                   float* __restrict__ out_masks) {
    const int gw   = (blockIdx.x * blockDim.x + threadIdx.x) >> 5;
    const int lane = threadIdx.x & 31;
    if (gw >= NROWS) return;
    const int n = gw;
    const int b = n >> 9;
    const int t = n & 511;

    float xr[16], prior[16];
    const float* xp = x + (size_t)n * E;
    #pragma unroll
    for (int j = 0; j < 16; j++) {
        xr[j]    = xp[lane + 32 * j];
        prior[j] = 1.0f;
    }

    for (int h = 0; h < H; h++) {
        const float* Lp  = g_logits + ((size_t)h * NROWS + n) * E;
        const float* scp = g_scale + h * E;
        const float* shp = g_shift + h * E;

        float z[16];
        float m = -1e30f;
        #pragma unroll
        for (int j = 0; j < 16; j++) {
            const int o = lane + 32 * j;
            float v = fmaf(Lp[o], scp[o], shp[o]) * prior[j];
            z[j] = v;
            m = fmaxf(m, v);
        }
        #pragma unroll
        for (int off = 16; off; off >>= 1)
            m = fmaxf(m, __shfl_xor_sync(0xffffffffu, m, off));

        float tau = m - 1.0f;
        for (int it = 0; it < 64; it++) {
            float S = 0.f, K = 0.f;
            #pragma unroll
            for (int j = 0; j < 16; j++) {
                if (z[j] > tau) { S += z[j]; K += 1.0f; }
            }
            #pragma unroll
            for (int off = 16; off; off >>= 1) {
                S += __shfl_xor_sync(0xffffffffu, S, off);
                K += __shfl_xor_sync(0xffffffffu, K, off);
            }
            float tnew = (S - 1.0f) / K;
            if (!(tnew > tau)) break;
            tau = tnew;
        }

        float* om = out_masked + ((size_t)h * NROWS + n) * E;              // (H,B,T,E)
        float* ok = out_masks  + (((size_t)b * H + h) * 512 + t) * E;      // (B,H,T,E)
        #pragma unroll
        for (int j = 0; j < 16; j++) {
            const int o = lane + 32 * j;
            float mask = fmaxf(z[j] - tau, 0.0f);
            om[o] = xr[j] * mask;
            ok[o] = mask;
            prior[j] *= fmaxf(GAMMA - mask, 0.0f);
        }
    }
}

// ---------------------------------------------------------------------------
extern "C" void kernel_launch(void* const* d_in, const int* in_sizes, int n_in,
                              void* d_out, int out_size) {
    const float* x  = (const float*)d_in[0];
    const float* W  = (const float*)d_in[1];
    const float* bw = (const float*)d_in[2];
    const float* bb = (const float*)d_in[3];
    float* out_masked = (float*)d_out;                                  // (H,B,T,E)
    float* out_masks  = (float*)d_out + (size_t)H * NROWS * E;          // (B,H,T,E)

    cudaFuncSetAttribute(gemm_kernel, cudaFuncAttributeMaxDynamicSharedMemorySize, SMEM_TOTAL);

    split_x_kernel<<<(NROWS * E / 4) / 256, 256>>>(x);
    split_w_kernel<<<(H * E * E / 4) / 256, 256>>>(W);

    dim3 ggrid(NROWS / BM, E / BN, H);
    gemm_kernel<<<ggrid, 256, SMEM_TOTAL>>>();

    bnstats_kernel<<<H * NCHUNK, 512>>>();
    finalize_kernel<<<H, 512>>>(bw, bb);
    scan_kernel<<<NROWS / 8, 256>>>(x, out_masked, out_masks);
}

// round 5
// speedup vs baseline: 3.3942x; 1.0613x over previous
#include <cuda_runtime.h>
#include <cuda_fp16.h>
#include <math.h>
#include <stdint.h>

#define NROWS 16384   // B*T
#define E     512
#define H     8
#define BN_EPS 1e-5f
#define GAMMA  1.5f

#define BM 128
#define BN 128
#define BK 32
#define NSTAGE 3
#define NMT   (NROWS / BM)            // 128 m-tiles
#define TILE_B (BM * BK * 2)          // 8192 bytes per tile
#define STAGE_B (4 * TILE_B)          // 32768 (xh, xl, wh, wl)
#define SMEM_TOTAL (NSTAGE * STAGE_B) // 98304

// ---------------- static device scratch (no allocation) ----------------
__device__ float g_logits[(size_t)H * NROWS * E];   // 268 MB
__device__ float g_psum[(size_t)H * NMT * E];
__device__ float g_psq [(size_t)H * NMT * E];
__device__ float g_scale[H * E];
__device__ float g_shift[H * E];
__device__ __half g_xhi[(size_t)NROWS * E];
__device__ __half g_xlo[(size_t)NROWS * E];
__device__ __half g_whi[(size_t)H * E * E];
__device__ __half g_wlo[(size_t)H * E * E];

// ---------------- PTX helpers ----------------
static __device__ __forceinline__ uint32_t smem_u32(const void* p) {
    uint32_t a;
    asm("{ .reg .u64 t; cvta.to.shared.u64 t, %1; cvt.u32.u64 %0, t; }" : "=r"(a) : "l"(p));
    return a;
}
static __device__ __forceinline__ void cp_async16(uint32_t dst, const void* src) {
    asm volatile("cp.async.cg.shared.global [%0], [%1], 16;" :: "r"(dst), "l"(src) : "memory");
}
static __device__ __forceinline__ void cp_commit() {
    asm volatile("cp.async.commit_group;" ::: "memory");
}
template <int N>
static __device__ __forceinline__ void cp_wait() {
    asm volatile("cp.async.wait_group %0;" :: "n"(N) : "memory");
}
static __device__ __forceinline__ void ldsm4(uint32_t* r, uint32_t addr) {
    asm volatile("ldmatrix.sync.aligned.m8n8.x4.shared.b16 {%0,%1,%2,%3}, [%4];"
                 : "=r"(r[0]), "=r"(r[1]), "=r"(r[2]), "=r"(r[3]) : "r"(addr));
}
static __device__ __forceinline__ void mma16816(float* d, const uint32_t* a, const uint32_t* b) {
    asm volatile(
        "mma.sync.aligned.m16n8k16.row.col.f32.f16.f16.f32 "
        "{%0,%1,%2,%3}, {%4,%5,%6,%7}, {%8,%9}, {%0,%1,%2,%3};"
        : "+f"(d[0]), "+f"(d[1]), "+f"(d[2]), "+f"(d[3])
        : "r"(a[0]), "r"(a[1]), "r"(a[2]), "r"(a[3]), "r"(b[0]), "r"(b[1]));
}

// 64B-row swizzle: 16B chunk c of row r stored at chunk (c ^ ((r>>1)&3))
static __device__ __forceinline__ uint32_t swz(int row, int ch) {
    return (uint32_t)((row << 6) + (((ch ^ (row >> 1)) & 3) << 4));
}

// ---------------------------------------------------------------------------
// fp16 hi/lo split kernels: v = hi + lo (each fp16-rounded)
// ---------------------------------------------------------------------------
static __device__ __forceinline__ void split4h(const float4 v, __half* hi, __half* lo, size_t i) {
    float a[4] = {v.x, v.y, v.z, v.w};
    uint32_t ph[2], pl[2];
    #pragma unroll
    for (int p = 0; p < 2; p++) {
        __half h0 = __float2half_rn(a[2*p+0]);
        __half h1 = __float2half_rn(a[2*p+1]);
        __half l0 = __float2half_rn(a[2*p+0] - __half2float(h0));
        __half l1 = __float2half_rn(a[2*p+1] - __half2float(h1));
        ph[p] = ((uint32_t)__half_as_ushort(h1) << 16) | __half_as_ushort(h0);
        pl[p] = ((uint32_t)__half_as_ushort(l1) << 16) | __half_as_ushort(l0);
    }
    *(uint2*)(hi + i) = make_uint2(ph[0], ph[1]);
    *(uint2*)(lo + i) = make_uint2(pl[0], pl[1]);
}
__global__ void __launch_bounds__(256) split_x_kernel(const float* __restrict__ x) {
    size_t i = ((size_t)blockIdx.x * 256 + threadIdx.x) * 4;
    split4h(*(const float4*)(x + i), g_xhi, g_xlo, i);
}
__global__ void __launch_bounds__(256) split_w_kernel(const float* __restrict__ w) {
    size_t i = ((size_t)blockIdx.x * 256 + threadIdx.x) * 4;
    split4h(*(const float4*)(w + i), g_whi, g_wlo, i);
}

// ---------------------------------------------------------------------------
// HMMA GEMM + fused BN partial stats, fp16x3:
//   logits = xh*wh + xh*wl + xl*wh  (fp32 accumulate; dropped xl*wl ~ 2^-22)
// CTA 128x128, BK=32, 3-stage cp.async, 8 warps (2 M x 4 N), warp tile 64x32.
// ---------------------------------------------------------------------------
__global__ void __launch_bounds__(256, 2) gemm_kernel() {
    extern __shared__ __align__(1024) char smem[];
    const uint32_t sb = smem_u32(smem);
    const int tid  = threadIdx.x;
    const int lane = tid & 31;
    const int wid  = tid >> 5;
    const int wm   = wid & 1;
    const int wn   = wid >> 1;
    const int bm   = blockIdx.x;
    const int m0   = bm * BM;
    const int o0   = blockIdx.y * BN;
    const int h    = blockIdx.z;

    const __half* gx_hi = g_xhi + (size_t)m0 * E;
    const __half* gx_lo = g_xlo + (size_t)m0 * E;
    const __half* gw_hi = g_whi + ((size_t)h * E + o0) * E;
    const __half* gw_lo = g_wlo + ((size_t)h * E + o0) * E;

    const int trow = tid >> 2;   // 0..63
    const int tc   = tid & 3;    // 16B chunk 0..3

    float C[4][4][4];
    #pragma unroll
    for (int i = 0; i < 4; i++)
        #pragma unroll
        for (int j = 0; j < 4; j++)
            #pragma unroll
            for (int k = 0; k < 4; k++) C[i][j][k] = 0.f;

    auto load_stage = [&](int s, int k0) {
        const uint32_t base = sb + s * STAGE_B;
        const size_t koff = (size_t)k0 + tc * 8;
        #pragma unroll
        for (int i = 0; i < 2; i++) {
            const int row = trow + i * 64;
            const uint32_t o = swz(row, tc);
            const size_t go = (size_t)row * E + koff;
            cp_async16(base + o,              gx_hi + go);
            cp_async16(base + TILE_B + o,     gx_lo + go);
            cp_async16(base + 2 * TILE_B + o, gw_hi + go);
            cp_async16(base + 3 * TILE_B + o, gw_lo + go);
        }
    };

    auto compute_stage = [&](int s) {
        const uint32_t aHiB = sb + s * STAGE_B;
        const uint32_t aLoB = aHiB + TILE_B;
        const uint32_t bHiB = aHiB + 2 * TILE_B;
        const uint32_t bLoB = aHiB + 3 * TILE_B;
        #pragma unroll
        for (int ks = 0; ks < 2; ks++) {
            uint32_t ahi[4][4], alo[4][4], b[4][2];
            #pragma unroll
            for (int mi = 0; mi < 4; mi++) {
                const int row = wm * 64 + mi * 16 + (lane & 15);
                const int ch  = ks * 2 + (lane >> 4);
                const uint32_t off = swz(row, ch);
                ldsm4(ahi[mi], aHiB + off);
                ldsm4(alo[mi], aLoB + off);
            }
            // B-hi: two products (xh*wh, xl*wh)
            #pragma unroll
            for (int p = 0; p < 2; p++) {
                const int row = wn * 32 + p * 16 + (lane & 7) + ((lane >> 4) << 3);
                const int ch  = ks * 2 + ((lane >> 3) & 1);
                uint32_t r[4];
                ldsm4(r, bHiB + swz(row, ch));
                b[2*p][0] = r[0];   b[2*p][1] = r[1];
                b[2*p+1][0] = r[2]; b[2*p+1][1] = r[3];
            }
            #pragma unroll
            for (int mi = 0; mi < 4; mi++)
                #pragma unroll
                for (int nj = 0; nj < 4; nj++) {
                    mma16816(C[mi][nj], ahi[mi], b[nj]);
                    mma16816(C[mi][nj], alo[mi], b[nj]);
                }
            // B-lo: one product (xh*wl); reuse b regs
            #pragma unroll
            for (int p = 0; p < 2; p++) {
                const int row = wn * 32 + p * 16 + (lane & 7) + ((lane >> 4) << 3);
                const int ch  = ks * 2 + ((lane >> 3) & 1);
                uint32_t r[4];
                ldsm4(r, bLoB + swz(row, ch));
                b[2*p][0] = r[0];   b[2*p][1] = r[1];
                b[2*p+1][0] = r[2]; b[2*p+1][1] = r[3];
            }
            #pragma unroll
            for (int mi = 0; mi < 4; mi++)
                #pragma unroll
                for (int nj = 0; nj < 4; nj++)
                    mma16816(C[mi][nj], ahi[mi], b[nj]);
        }
    };

    load_stage(0, 0); cp_commit();
    load_stage(1, BK); cp_commit();

    int ls = 2, cs = 0;
    #pragma unroll 1
    for (int c = 0; c < E / BK; c++) {
        cp_wait<1>();
        __syncthreads();
        if (c + 2 < E / BK) load_stage(ls, (c + 2) * BK);
        cp_commit();
        compute_stage(cs);
        ls = (ls == NSTAGE - 1) ? 0 : ls + 1;
        cs = (cs == NSTAGE - 1) ? 0 : cs + 1;
    }

    // ---- epilogue: store logits + per-CTA column stats ----
    float* Cg = g_logits + (size_t)h * NROWS * E;
    const int rb = m0 + wm * 64;
    const int cb = o0 + wn * 32;
    #pragma unroll
    for (int mi = 0; mi < 4; mi++) {
        const int r = rb + mi * 16 + (lane >> 2);
        #pragma unroll
        for (int nj = 0; nj < 4; nj++) {
            const int col = cb + nj * 8 + 2 * (lane & 3);
            *(float2*)(Cg + (size_t)r * E + col)       = make_float2(C[mi][nj][0], C[mi][nj][1]);
            *(float2*)(Cg + (size_t)(r + 8) * E + col) = make_float2(C[mi][nj][2], C[mi][nj][3]);
        }
    }

    // column partial sums over this CTA's 128 rows (deterministic)
    float s[4][2], q[4][2];
    #pragma unroll
    for (int nj = 0; nj < 4; nj++) { s[nj][0] = s[nj][1] = q[nj][0] = q[nj][1] = 0.f; }
    #pragma unroll
    for (int mi = 0; mi < 4; mi++)
        #pragma unroll
        for (int nj = 0; nj < 4; nj++) {
            float v0 = C[mi][nj][0], v1 = C[mi][nj][1], v2 = C[mi][nj][2], v3 = C[mi][nj][3];
            s[nj][0] += v0 + v2; q[nj][0] += v0 * v0 + v2 * v2;
            s[nj][1] += v1 + v3; q[nj][1] += v1 * v1 + v3 * v3;
        }
    #pragma unroll
    for (int off = 4; off < 32; off <<= 1)
        #pragma unroll
        for (int nj = 0; nj < 4; nj++) {
            s[nj][0] += __shfl_xor_sync(0xffffffffu, s[nj][0], off);
            s[nj][1] += __shfl_xor_sync(0xffffffffu, s[nj][1], off);
            q[nj][0] += __shfl_xor_sync(0xffffffffu, q[nj][0], off);
            q[nj][1] += __shfl_xor_sync(0xffffffffu, q[nj][1], off);
        }

    __syncthreads();                      // done reading tiles; reuse smem
    float* red = (float*)smem;            // [2(wm)][128(col)][2(stat)]
    if (lane < 4) {
        #pragma unroll
        for (int nj = 0; nj < 4; nj++)
            #pragma unroll
            for (int e = 0; e < 2; e++) {
                const int col = wn * 32 + nj * 8 + 2 * lane + e;
                red[(wm * 128 + col) * 2 + 0] = s[nj][e];
                red[(wm * 128 + col) * 2 + 1] = q[nj][e];
            }
    }
    __syncthreads();
    {
        const int col = tid >> 1;
        const int st  = tid & 1;
        const float v = red[(0 * 128 + col) * 2 + st] + red[(1 * 128 + col) * 2 + st];
        float* dst = st ? g_psq : g_psum;
        dst[((size_t)h * NMT + bm) * E + o0 + col] = v;
    }
}

// ---------------------------------------------------------------------------
// finalize: reduce NMT partials -> scale/shift
// ---------------------------------------------------------------------------
__global__ void __launch_bounds__(512) finalize_kernel(const float* __restrict__ bw,
                                                       const float* __restrict__ bb) {
    const int h = blockIdx.x;
    const int o = threadIdx.x;
    float s = 0.f, s2 = 0.f;
    for (int c = 0; c < NMT; c++) {
        s  += g_psum[((size_t)h * NMT + c) * E + o];
        s2 += g_psq [((size_t)h * NMT + c) * E + o];
    }
    const float inv_n = 1.0f / (float)NROWS;
    float mean = s * inv_n;
    float var  = fmaf(-mean, mean, s2 * inv_n);
    float istd = rsqrtf(var + BN_EPS);
    float sc   = bw[h * E + o] * istd;
    g_scale[h * E + o] = sc;
    g_shift[h * E + o] = fmaf(-mean, sc, bb[h * E + o]);
}

// ---------------------------------------------------------------------------
// Sequential head scan with sparsemax (Newton tau), one warp per row.
// ---------------------------------------------------------------------------
__global__ void __launch_bounds__(256) scan_kernel(const float* __restrict__ x,
                                                   float* __restrict__ out_masked,
                                                   float* __restrict__ out_masks) {
    const int gw   = (blockIdx.x * blockDim.x + threadIdx.x) >> 5;
    const int lane = threadIdx.x & 31;
    if (gw >= NROWS) return;
    const int n = gw;
    const int b = n >> 9;
    const int t = n & 511;

    float xr[16], prior[16];
    const float* xp = x + (size_t)n * E;
    #pragma unroll
    for (int j = 0; j < 16; j++) {
        xr[j]    = xp[lane + 32 * j];
        prior[j] = 1.0f;
    }

    for (int h = 0; h < H; h++) {
        const float* Lp  = g_logits + ((size_t)h * NROWS + n) * E;
        const float* scp = g_scale + h * E;
        const float* shp = g_shift + h * E;

        float z[16];
        float m = -1e30f;
        #pragma unroll
        for (int j = 0; j < 16; j++) {
            const int o = lane + 32 * j;
            float v = fmaf(Lp[o], scp[o], shp[o]) * prior[j];
            z[j] = v;
            m = fmaxf(m, v);
        }
        #pragma unroll
        for (int off = 16; off; off >>= 1)
            m = fmaxf(m, __shfl_xor_sync(0xffffffffu, m, off));

        float tau = m - 1.0f;
        for (int it = 0; it < 64; it++) {
            float S = 0.f, K = 0.f;
            #pragma unroll
            for (int j = 0; j < 16; j++) {
                if (z[j] > tau) { S += z[j]; K += 1.0f; }
            }
            #pragma unroll
            for (int off = 16; off; off >>= 1) {
                S += __shfl_xor_sync(0xffffffffu, S, off);
                K += __shfl_xor_sync(0xffffffffu, K, off);
            }
            float tnew = (S - 1.0f) / K;
            if (!(tnew > tau)) break;
            tau = tnew;
        }

        float* om = out_masked + ((size_t)h * NROWS + n) * E;              // (H,B,T,E)
        float* ok = out_masks  + (((size_t)b * H + h) * 512 + t) * E;      // (B,H,T,E)
        #pragma unroll
        for (int j = 0; j < 16; j++) {
            const int o = lane + 32 * j;
            float mask = fmaxf(z[j] - tau, 0.0f);
            om[o] = xr[j] * mask;
            ok[o] = mask;
            prior[j] *= fmaxf(GAMMA - mask, 0.0f);
        }
    }
}

// ---------------------------------------------------------------------------
extern "C" void kernel_launch(void* const* d_in, const int* in_sizes, int n_in,
                              void* d_out, int out_size) {
    const float* x  = (const float*)d_in[0];
    const float* W  = (const float*)d_in[1];
    const float* bw = (const float*)d_in[2];
    const float* bb = (const float*)d_in[3];
    float* out_masked = (float*)d_out;                                  // (H,B,T,E)
    float* out_masks  = (float*)d_out + (size_t)H * NROWS * E;          // (B,H,T,E)

    cudaFuncSetAttribute(gemm_kernel, cudaFuncAttributeMaxDynamicSharedMemorySize, SMEM_TOTAL);

    split_x_kernel<<<(NROWS * E / 4) / 256, 256>>>(x);
    split_w_kernel<<<(H * E * E / 4) / 256, 256>>>(W);

    dim3 ggrid(NROWS / BM, E / BN, H);
    gemm_kernel<<<ggrid, 256, SMEM_TOTAL>>>();

    finalize_kernel<<<H, 512>>>(bw, bb);
    scan_kernel<<<NROWS / 8, 256>>>(x, out_masked, out_masks);
}